// round 14
// baseline (speedup 1.0000x reference)
#include <cuda_runtime.h>

// Convex_f: out[b,j,k] = (interior && Dy>0) ? 0.5*(y[j-1]+y[j+1]) - param[j]
//                                          : y[j] - param[j]   // bit-exact vs reference ((x+p)-p)
// where y = x + param, Dy = 2*y[j] - y[j-1] - y[j+1].
// Shapes: B=256, N=8192, K=16, float32, contiguous (B,N,K).
//
// R14: two-tile software pipeline inside each block, R8 primitives only.
// Tile A: 8 front-batched LDG.128 -> regs -> smem buf0 -> barrier.
// Then tile B's 16 raw LDG.128 are ISSUED before computing A, so the
// scoreboarded loads stream to DRAM while A's compute/store runs.
// B is converted/published to buf1 afterward. One barrier per tile (= R8).

constexpr int Bn = 256;
constexpr int Nn = 8192;
constexpr int KV = 4;                 // float4 per (b,j) row
constexpr int TJ = 256;               // j-rows per tile
constexpr int TPB_N = Nn / TJ;        // 32 tiles per batch
constexpr int NT   = Bn * TPB_N;      // 8192 tiles
constexpr int GRID = NT / 2;          // 4096 blocks, 2 tiles each
constexpr int CB = 256;
constexpr int EPT = (TJ * KV) / CB;   // 4 float4 per thread per tile
constexpr int SROWS = (TJ + 2) * KV;  // 1032

__global__ __launch_bounds__(CB, 3)   // reg cap 85: room for A-state + B raw batch
void convex_kernel(const float4* __restrict__ x4,
                   const float4* __restrict__ p4,
                   float4* __restrict__ o4)
{
    __shared__ float4 ys[2][SROWS];   // row jl stored at (jl+1)

    int tid = threadIdx.x;
    int tA  = blockIdx.x;             // tile A
    int tB  = blockIdx.x + GRID;      // tile B

    // ---- tile A: load batch (8 LDG.128) + halo, publish y to buf0 ----
    int bA    = tA >> 5;
    int jtA   = (tA & (TPB_N - 1)) * TJ;
    int baseA = bA * (Nn * KV) + jtA * KV;

    float4 pAr[EPT], yAr[EPT];
    #pragma unroll
    for (int r = 0; r < EPT; r++) {
        int flat = r * CB + tid;
        float4 xv = x4[baseA + flat];
        float4 pv = p4[baseA + flat];
        pAr[r] = pv;
        yAr[r] = make_float4(xv.x + pv.x, xv.y + pv.y, xv.z + pv.z, xv.w + pv.w);
    }
    if (tid < 2 * KV) {               // halo rows j=-1, TJ (clamped; never consumed at edges)
        int kvh = tid & (KV - 1);
        bool hi = tid >= KV;
        int jg  = hi ? (jtA + TJ) : (jtA - 1);
        jg = (jg < 0) ? 0 : ((jg > Nn - 1) ? (Nn - 1) : jg);
        int offh = bA * (Nn * KV) + jg * KV + kvh;
        float4 xv = x4[offh];
        float4 pv = p4[offh];
        int slot = hi ? ((TJ + 1) * KV + kvh) : kvh;
        ys[0][slot] = make_float4(xv.x + pv.x, xv.y + pv.y, xv.z + pv.z, xv.w + pv.w);
    }
    #pragma unroll
    for (int r = 0; r < EPT; r++) {
        int flat = r * CB + tid;
        ys[0][flat + KV] = yAr[r];
    }
    __syncthreads();

    // ---- issue tile B raw loads (16 LDG.128) BEFORE computing A ----
    int bB    = tB >> 5;
    int jtB   = (tB & (TPB_N - 1)) * TJ;
    int baseB = bB * (Nn * KV) + jtB * KV;

    float4 xBr[EPT], pBr[EPT];
    #pragma unroll
    for (int r = 0; r < EPT; r++) {
        int flat = r * CB + tid;
        xBr[r] = x4[baseB + flat];
        pBr[r] = p4[baseB + flat];
    }
    float4 hxB, hpB;
    int hslotB = 0;
    bool hval = tid < 2 * KV;
    if (hval) {
        int kvh = tid & (KV - 1);
        bool hi = tid >= KV;
        int jg  = hi ? (jtB + TJ) : (jtB - 1);
        jg = (jg < 0) ? 0 : ((jg > Nn - 1) ? (Nn - 1) : jg);
        int offh = bB * (Nn * KV) + jg * KV + kvh;
        hxB = x4[offh];
        hpB = p4[offh];
        hslotB = hi ? ((TJ + 1) * KV + kvh) : kvh;
    }

    // ---- compute tile A (B loads in flight underneath) ----
    #pragma unroll
    for (int r = 0; r < EPT; r++) {
        int flat = r * CB + tid;
        int j    = jtA + (flat >> 2);
        float4 y0 = yAr[r];
        float4 p0 = pAr[r];
        float4 ym = ys[0][flat];
        float4 yp = ys[0][flat + 2 * KV];
        bool interior = (j > 0) && (j < Nn - 1);

        float4 out;
        { float s = ym.x + yp.x; float Dy = fmaf(2.0f, y0.x, -s);
          float alt = fmaf(0.5f, s, -p0.x); float keep = y0.x - p0.x;
          out.x = (interior && Dy > 0.0f) ? alt : keep; }
        { float s = ym.y + yp.y; float Dy = fmaf(2.0f, y0.y, -s);
          float alt = fmaf(0.5f, s, -p0.y); float keep = y0.y - p0.y;
          out.y = (interior && Dy > 0.0f) ? alt : keep; }
        { float s = ym.z + yp.z; float Dy = fmaf(2.0f, y0.z, -s);
          float alt = fmaf(0.5f, s, -p0.z); float keep = y0.z - p0.z;
          out.z = (interior && Dy > 0.0f) ? alt : keep; }
        { float s = ym.w + yp.w; float Dy = fmaf(2.0f, y0.w, -s);
          float alt = fmaf(0.5f, s, -p0.w); float keep = y0.w - p0.w;
          out.w = (interior && Dy > 0.0f) ? alt : keep; }

        o4[baseA + flat] = out;
    }

    // ---- convert + publish tile B to buf1 ----
    float4 yBr[EPT];
    #pragma unroll
    for (int r = 0; r < EPT; r++) {
        yBr[r] = make_float4(xBr[r].x + pBr[r].x, xBr[r].y + pBr[r].y,
                             xBr[r].z + pBr[r].z, xBr[r].w + pBr[r].w);
        int flat = r * CB + tid;
        ys[1][flat + KV] = yBr[r];
    }
    if (hval) {
        ys[1][hslotB] = make_float4(hxB.x + hpB.x, hxB.y + hpB.y,
                                    hxB.z + hpB.z, hxB.w + hpB.w);
    }
    __syncthreads();

    // ---- compute tile B ----
    #pragma unroll
    for (int r = 0; r < EPT; r++) {
        int flat = r * CB + tid;
        int j    = jtB + (flat >> 2);
        float4 y0 = yBr[r];
        float4 p0 = pBr[r];
        float4 ym = ys[1][flat];
        float4 yp = ys[1][flat + 2 * KV];
        bool interior = (j > 0) && (j < Nn - 1);

        float4 out;
        { float s = ym.x + yp.x; float Dy = fmaf(2.0f, y0.x, -s);
          float alt = fmaf(0.5f, s, -p0.x); float keep = y0.x - p0.x;
          out.x = (interior && Dy > 0.0f) ? alt : keep; }
        { float s = ym.y + yp.y; float Dy = fmaf(2.0f, y0.y, -s);
          float alt = fmaf(0.5f, s, -p0.y); float keep = y0.y - p0.y;
          out.y = (interior && Dy > 0.0f) ? alt : keep; }
        { float s = ym.z + yp.z; float Dy = fmaf(2.0f, y0.z, -s);
          float alt = fmaf(0.5f, s, -p0.z); float keep = y0.z - p0.z;
          out.z = (interior && Dy > 0.0f) ? alt : keep; }
        { float s = ym.w + yp.w; float Dy = fmaf(2.0f, y0.w, -s);
          float alt = fmaf(0.5f, s, -p0.w); float keep = y0.w - p0.w;
          out.w = (interior && Dy > 0.0f) ? alt : keep; }

        o4[baseB + flat] = out;
    }
}

extern "C" void kernel_launch(void* const* d_in, const int* in_sizes, int n_in,
                              void* d_out, int out_size)
{
    const float4* x4 = (const float4*)d_in[0];
    const float4* p4 = (const float4*)d_in[1];
    float4* o4 = (float4*)d_out;

    convex_kernel<<<GRID, CB>>>(x4, p4, o4);
}

// round 16
// speedup vs baseline: 1.1104x; 1.1104x over previous
#include <cuda_runtime.h>

// Convex_f: out[b,j,k] = (interior && Dy>0) ? 0.5*(y[j-1]+y[j+1]) - param[j]
//                                          : y[j] - param[j]   // bit-exact vs reference ((x+p)-p)
// where y = x + param, Dy = 2*y[j] - y[j-1] - y[j+1].
// Shapes: B=256, N=8192, K=16, float32, contiguous (B,N,K).
//
// R15 = champion R8 + __ldcs (evict-first) on the streaming reads.
// Reads are use-once; keeping them from occupying L2 leaves more capacity
// to absorb the output writes (measured: ~55MB of writes stay dirty in L2
// during the kernel window at 53us), cutting in-window DRAM traffic.
// Stores stay default-cached (evicting them early would ADD writebacks).

constexpr int Bn = 256;
constexpr int Nn = 8192;
constexpr int KV = 4;                 // float4 per (b,j) row
constexpr int TJ = 256;               // j-rows per block tile
constexpr int TILES_PER_B = Nn / TJ;  // 32
constexpr int CB = 256;               // threads per block
constexpr int EPT = (TJ * KV) / CB;   // float4 elements per thread = 4

__global__ __launch_bounds__(CB, 5)
void convex_kernel(const float4* __restrict__ x4,
                   const float4* __restrict__ p4,
                   float4* __restrict__ o4)
{
    // y tile with one halo row on each side: rows [-1 .. TJ], row jl at (jl+1)
    __shared__ float4 ys[(TJ + 2) * KV];

    int tile = blockIdx.x;
    int b    = tile >> 5;                  // tile / TILES_PER_B
    int jt   = (tile & (TILES_PER_B - 1)) * TJ;
    int base = b * (Nn * KV) + jt * KV;    // float4 offset of (b, jt, k=0)
    int tid  = threadIdx.x;

    // ---- Load phase: 8 independent LDG.128 per thread, fully coalesced ----
    float4 pr[EPT];
    float4 yr[EPT];
    #pragma unroll
    for (int r = 0; r < EPT; r++) {
        int flat = r * CB + tid;           // = j_local*KV + kv
        float4 xv = __ldcs(&x4[base + flat]);
        float4 pv = __ldcs(&p4[base + flat]);
        pr[r] = pv;
        yr[r] = make_float4(xv.x + pv.x, xv.y + pv.y, xv.z + pv.z, xv.w + pv.w);
    }

    // Halo rows: j_local = -1 and j_local = TJ (clamped at global edges;
    // clamped values are never consumed because those j are non-interior).
    if (tid < 2 * KV) {
        int kvh = tid & (KV - 1);
        bool hi = tid >= KV;
        int jg  = hi ? (jt + TJ) : (jt - 1);
        jg = (jg < 0) ? 0 : ((jg > Nn - 1) ? (Nn - 1) : jg);
        int offh = b * (Nn * KV) + jg * KV + kvh;
        float4 xv = __ldcs(&x4[offh]);
        float4 pv = __ldcs(&p4[offh]);
        int slot = hi ? ((TJ + 1) * KV + kvh) : kvh;
        ys[slot] = make_float4(xv.x + pv.x, xv.y + pv.y, xv.z + pv.z, xv.w + pv.w);
    }

    #pragma unroll
    for (int r = 0; r < EPT; r++) {
        int flat = r * CB + tid;
        ys[flat + KV] = yr[r];             // row jl stored at (jl+1)
    }

    __syncthreads();

    // ---- Compute phase: neighbors from smem, y0/p0 from regs, write out ----
    #pragma unroll
    for (int r = 0; r < EPT; r++) {
        int flat = r * CB + tid;
        int j    = jt + (flat >> 2);       // global j
        float4 y0 = yr[r];
        float4 p0 = pr[r];
        float4 ym = ys[flat];              // j-1
        float4 yp = ys[flat + 2 * KV];     // j+1

        bool interior = (j > 0) && (j < Nn - 1);

        float4 out;
        {
            float s    = ym.x + yp.x;
            float Dy   = fmaf(2.0f, y0.x, -s);
            float alt  = fmaf(0.5f, s, -p0.x);
            float keep = y0.x - p0.x;
            out.x = (interior && Dy > 0.0f) ? alt : keep;
        }
        {
            float s    = ym.y + yp.y;
            float Dy   = fmaf(2.0f, y0.y, -s);
            float alt  = fmaf(0.5f, s, -p0.y);
            float keep = y0.y - p0.y;
            out.y = (interior && Dy > 0.0f) ? alt : keep;
        }
        {
            float s    = ym.z + yp.z;
            float Dy   = fmaf(2.0f, y0.z, -s);
            float alt  = fmaf(0.5f, s, -p0.z);
            float keep = y0.z - p0.z;
            out.z = (interior && Dy > 0.0f) ? alt : keep;
        }
        {
            float s    = ym.w + yp.w;
            float Dy   = fmaf(2.0f, y0.w, -s);
            float alt  = fmaf(0.5f, s, -p0.w);
            float keep = y0.w - p0.w;
            out.w = (interior && Dy > 0.0f) ? alt : keep;
        }

        o4[base + flat] = out;
    }
}

extern "C" void kernel_launch(void* const* d_in, const int* in_sizes, int n_in,
                              void* d_out, int out_size)
{
    const float4* x4 = (const float4*)d_in[0];
    const float4* p4 = (const float4*)d_in[1];
    float4* o4 = (float4*)d_out;

    int blocks = Bn * TILES_PER_B;        // 8192
    convex_kernel<<<blocks, CB>>>(x4, p4, o4);
}

// round 17
// speedup vs baseline: 1.1282x; 1.0160x over previous
#include <cuda_runtime.h>

// Convex_f: out[b,j,k] = (interior && Dy>0) ? 0.5*(y[j-1]+y[j+1]) - param[j]
//                                          : y[j] - param[j]   // bit-exact vs reference ((x+p)-p)
// where y = x + param, Dy = 2*y[j] - y[j-1] - y[j+1].
// Shapes: B=256, N=8192, K=16, float32, contiguous (B,N,K).
//
// FINAL (= R8 champion, 62.2us, HBM 6.62TB/s / 83.5%):
// Block owns 256 consecutive j for one batch. Each thread front-batches
// 8 coalesced LDG.128 (4 x + 4 p), forms y, publishes it to a smem tile
// with 1-row halos, one barrier, then computes from smem neighbors with
// y0/p0 kept in registers. DRAM halo overhead 0.78% of reads.
// Default cache policy on all global accesses (ldcs measured slower, R15).

constexpr int Bn = 256;
constexpr int Nn = 8192;
constexpr int KV = 4;                 // float4 per (b,j) row
constexpr int TJ = 256;               // j-rows per block tile
constexpr int TILES_PER_B = Nn / TJ;  // 32
constexpr int CB = 256;               // threads per block
constexpr int EPT = (TJ * KV) / CB;   // float4 elements per thread = 4

__global__ __launch_bounds__(CB, 5)
void convex_kernel(const float4* __restrict__ x4,
                   const float4* __restrict__ p4,
                   float4* __restrict__ o4)
{
    // y tile with one halo row on each side: rows [-1 .. TJ], row jl at (jl+1)
    __shared__ float4 ys[(TJ + 2) * KV];

    int tile = blockIdx.x;
    int b    = tile >> 5;                  // tile / TILES_PER_B
    int jt   = (tile & (TILES_PER_B - 1)) * TJ;
    int base = b * (Nn * KV) + jt * KV;    // float4 offset of (b, jt, k=0)
    int tid  = threadIdx.x;

    // ---- Load phase: 8 independent LDG.128 per thread, fully coalesced ----
    float4 pr[EPT];
    float4 yr[EPT];
    #pragma unroll
    for (int r = 0; r < EPT; r++) {
        int flat = r * CB + tid;           // = j_local*KV + kv
        float4 xv = x4[base + flat];
        float4 pv = p4[base + flat];
        pr[r] = pv;
        yr[r] = make_float4(xv.x + pv.x, xv.y + pv.y, xv.z + pv.z, xv.w + pv.w);
    }

    // Halo rows: j_local = -1 and j_local = TJ (clamped at global edges;
    // clamped values are never consumed because those j are non-interior).
    if (tid < 2 * KV) {
        int kvh = tid & (KV - 1);
        bool hi = tid >= KV;
        int jg  = hi ? (jt + TJ) : (jt - 1);
        jg = (jg < 0) ? 0 : ((jg > Nn - 1) ? (Nn - 1) : jg);
        int offh = b * (Nn * KV) + jg * KV + kvh;
        float4 xv = x4[offh];
        float4 pv = p4[offh];
        int slot = hi ? ((TJ + 1) * KV + kvh) : kvh;
        ys[slot] = make_float4(xv.x + pv.x, xv.y + pv.y, xv.z + pv.z, xv.w + pv.w);
    }

    #pragma unroll
    for (int r = 0; r < EPT; r++) {
        int flat = r * CB + tid;
        ys[flat + KV] = yr[r];             // row jl stored at (jl+1)
    }

    __syncthreads();

    // ---- Compute phase: neighbors from smem, y0/p0 from regs, write out ----
    #pragma unroll
    for (int r = 0; r < EPT; r++) {
        int flat = r * CB + tid;
        int j    = jt + (flat >> 2);       // global j
        float4 y0 = yr[r];
        float4 p0 = pr[r];
        float4 ym = ys[flat];              // j-1
        float4 yp = ys[flat + 2 * KV];     // j+1

        bool interior = (j > 0) && (j < Nn - 1);

        float4 out;
        {
            float s    = ym.x + yp.x;
            float Dy   = fmaf(2.0f, y0.x, -s);
            float alt  = fmaf(0.5f, s, -p0.x);
            float keep = y0.x - p0.x;
            out.x = (interior && Dy > 0.0f) ? alt : keep;
        }
        {
            float s    = ym.y + yp.y;
            float Dy   = fmaf(2.0f, y0.y, -s);
            float alt  = fmaf(0.5f, s, -p0.y);
            float keep = y0.y - p0.y;
            out.y = (interior && Dy > 0.0f) ? alt : keep;
        }
        {
            float s    = ym.z + yp.z;
            float Dy   = fmaf(2.0f, y0.z, -s);
            float alt  = fmaf(0.5f, s, -p0.z);
            float keep = y0.z - p0.z;
            out.z = (interior && Dy > 0.0f) ? alt : keep;
        }
        {
            float s    = ym.w + yp.w;
            float Dy   = fmaf(2.0f, y0.w, -s);
            float alt  = fmaf(0.5f, s, -p0.w);
            float keep = y0.w - p0.w;
            out.w = (interior && Dy > 0.0f) ? alt : keep;
        }

        o4[base + flat] = out;
    }
}

extern "C" void kernel_launch(void* const* d_in, const int* in_sizes, int n_in,
                              void* d_out, int out_size)
{
    const float4* x4 = (const float4*)d_in[0];
    const float4* p4 = (const float4*)d_in[1];
    float4* o4 = (float4*)d_out;

    int blocks = Bn * TILES_PER_B;        // 8192
    convex_kernel<<<blocks, CB>>>(x4, p4, o4);
}